// round 7
// baseline (speedup 1.0000x reference)
#include <cuda_runtime.h>

#define N_NODES 100000
#define N_EDGES 3200000
#define D_IN    256
#define D_OUT   128
#define LN_EPS  1e-5f

#define BM 64
#define BK 32

// ---------------- static device scratch (no runtime allocation) ----------------
__device__ float g_support[(size_t)N_NODES * D_OUT];   // x @ W
__device__ float g_base[(size_t)N_NODES * D_OUT];      // bias + relu(x @ res_w + res_b)
__device__ int   g_count[N_NODES];
__device__ int   g_offsets[N_NODES];
__device__ int   g_cursor[N_NODES];
__device__ int   g_perm[N_EDGES];
__device__ int   g_partials[128];

// ---------------- f32x2 packed-math helpers (FFMA2 path) ----------------
__device__ __forceinline__ unsigned long long dup2(float a) {
    unsigned long long r;
    unsigned int ai = __float_as_uint(a);
    asm("mov.b64 %0, {%1, %1};" : "=l"(r) : "r"(ai));
    return r;
}
__device__ __forceinline__ void fma2(unsigned long long& d, unsigned long long a,
                                     unsigned long long b) {
    asm("fma.rn.f32x2 %0, %1, %2, %0;" : "+l"(d) : "l"(a), "l"(b));
}
__device__ __forceinline__ float2 unpack2(unsigned long long v) {
    unsigned int lo, hi;
    asm("mov.b64 {%0, %1}, %2;" : "=r"(lo), "=r"(hi) : "l"(v));
    float2 r;
    r.x = __uint_as_float(lo);
    r.y = __uint_as_float(hi);
    return r;
}

// ---------------- kernel 1: fused dual GEMM ----------------
// support[n,:] = x[n,:] @ W          (D_IN x D_OUT)
// base[n,:]    = bias + relu(x[n,:] @ Rw + resb)
__global__ void __launch_bounds__(256, 2)
k_gemm(const float* __restrict__ x, const float* __restrict__ W,
       const float* __restrict__ Rw, const float* __restrict__ bias,
       const float* __restrict__ resb) {
    __shared__ float xs[BM][BK + 1];
    __shared__ __align__(16) float ws[BK][D_OUT];
    __shared__ __align__(16) float rs[BK][D_OUT];

    const int tid = threadIdx.x;          // 256 threads
    const int tx  = tid & 15;             // column group: cols tx*8 .. tx*8+7
    const int ty  = tid >> 4;             // rows ty + 16*i, i=0..3
    const int rowBase = blockIdx.x * BM;

    unsigned long long accW[4][4], accR[4][4];
#pragma unroll
    for (int i = 0; i < 4; i++)
#pragma unroll
        for (int j = 0; j < 4; j++) { accW[i][j] = 0ull; accR[i][j] = 0ull; }

    for (int k0 = 0; k0 < D_IN; k0 += BK) {
        // load x tile 64x32 (512 float4 -> 2 per thread), guard tail rows
#pragma unroll
        for (int f = tid; f < BM * BK / 4; f += 256) {
            int r = f >> 3;
            int c = (f & 7) * 4;
            float4 v = make_float4(0.f, 0.f, 0.f, 0.f);
            int row = rowBase + r;
            if (row < N_NODES)
                v = *(const float4*)(x + (size_t)row * D_IN + k0 + c);
            xs[r][c + 0] = v.x; xs[r][c + 1] = v.y;
            xs[r][c + 2] = v.z; xs[r][c + 3] = v.w;
        }
        // load W,R tiles 32x128 (1024 float4 each -> 4 per thread)
#pragma unroll
        for (int f = tid; f < BK * D_OUT / 4; f += 256) {
            int r = f >> 5;
            int c = (f & 31) * 4;
            *(float4*)&ws[r][c] = *(const float4*)(W  + (size_t)(k0 + r) * D_OUT + c);
            *(float4*)&rs[r][c] = *(const float4*)(Rw + (size_t)(k0 + r) * D_OUT + c);
        }
        __syncthreads();

#pragma unroll 8
        for (int k = 0; k < BK; k++) {
            unsigned long long a2[4];
#pragma unroll
            for (int i = 0; i < 4; i++) a2[i] = dup2(xs[ty + 16 * i][k]);
            // conflict-free LDS.128: 16 distinct 32B-aligned addresses per warp
            ulonglong2 w0 = *(const ulonglong2*)&ws[k][tx * 8];
            ulonglong2 w1 = *(const ulonglong2*)&ws[k][tx * 8 + 4];
            ulonglong2 r0 = *(const ulonglong2*)&rs[k][tx * 8];
            ulonglong2 r1 = *(const ulonglong2*)&rs[k][tx * 8 + 4];
#pragma unroll
            for (int i = 0; i < 4; i++) {
                fma2(accW[i][0], a2[i], w0.x);
                fma2(accW[i][1], a2[i], w0.y);
                fma2(accW[i][2], a2[i], w1.x);
                fma2(accW[i][3], a2[i], w1.y);
                fma2(accR[i][0], a2[i], r0.x);
                fma2(accR[i][1], a2[i], r0.y);
                fma2(accR[i][2], a2[i], r1.x);
                fma2(accR[i][3], a2[i], r1.y);
            }
        }
        __syncthreads();
    }

    // epilogue
    const float4 b0  = *(const float4*)(bias + tx * 8);
    const float4 b1  = *(const float4*)(bias + tx * 8 + 4);
    const float4 rb0 = *(const float4*)(resb + tx * 8);
    const float4 rb1 = *(const float4*)(resb + tx * 8 + 4);
#pragma unroll
    for (int i = 0; i < 4; i++) {
        int row = rowBase + ty + 16 * i;
        if (row >= N_NODES) continue;
        float2 s0 = unpack2(accW[i][0]), s1 = unpack2(accW[i][1]);
        float2 s2 = unpack2(accW[i][2]), s3 = unpack2(accW[i][3]);
        float2 t0 = unpack2(accR[i][0]), t1 = unpack2(accR[i][1]);
        float2 t2 = unpack2(accR[i][2]), t3 = unpack2(accR[i][3]);

        float* supp = g_support + (size_t)row * D_OUT + tx * 8;
        *(float4*)(supp)     = make_float4(s0.x, s0.y, s1.x, s1.y);
        *(float4*)(supp + 4) = make_float4(s2.x, s2.y, s3.x, s3.y);

        float* bp = g_base + (size_t)row * D_OUT + tx * 8;
        float4 bv0, bv1;
        bv0.x = b0.x + fmaxf(t0.x + rb0.x, 0.f);
        bv0.y = b0.y + fmaxf(t0.y + rb0.y, 0.f);
        bv0.z = b0.z + fmaxf(t1.x + rb0.z, 0.f);
        bv0.w = b0.w + fmaxf(t1.y + rb0.w, 0.f);
        bv1.x = b1.x + fmaxf(t2.x + rb1.x, 0.f);
        bv1.y = b1.y + fmaxf(t2.y + rb1.y, 0.f);
        bv1.z = b1.z + fmaxf(t3.x + rb1.z, 0.f);
        bv1.w = b1.w + fmaxf(t3.y + rb1.w, 0.f);
        *(float4*)(bp)     = bv0;
        *(float4*)(bp + 4) = bv1;
    }
}

// ---------------- counting sort pipeline ----------------
__global__ void k_zero_count() {
    int i = blockIdx.x * blockDim.x + threadIdx.x;
    if (i < N_NODES) g_count[i] = 0;
}

__global__ void k_hist(const int* __restrict__ dst) {
    int e = blockIdx.x * blockDim.x + threadIdx.x;
    if (e < N_EDGES) atomicAdd(&g_count[dst[e]], 1);
}

__global__ void k_scan1() {  // per-block exclusive scan, 98 blocks x 1024
    __shared__ int s[1024];
    int i = blockIdx.x * 1024 + threadIdx.x;
    int v = (i < N_NODES) ? g_count[i] : 0;
    s[threadIdx.x] = v;
    __syncthreads();
#pragma unroll
    for (int off = 1; off < 1024; off <<= 1) {
        int t = (threadIdx.x >= off) ? s[threadIdx.x - off] : 0;
        __syncthreads();
        s[threadIdx.x] += t;
        __syncthreads();
    }
    if (i < N_NODES) g_offsets[i] = s[threadIdx.x] - v;   // exclusive
    if (threadIdx.x == 1023) g_partials[blockIdx.x] = s[1023];
}

__global__ void k_scan2() {  // single block scans 98 partials (128 threads)
    __shared__ int s[128];
    int nblk = (N_NODES + 1023) / 1024;   // 98
    int v = (threadIdx.x < nblk) ? g_partials[threadIdx.x] : 0;
    s[threadIdx.x] = v;
    __syncthreads();
#pragma unroll
    for (int off = 1; off < 128; off <<= 1) {
        int t = (threadIdx.x >= off) ? s[threadIdx.x - off] : 0;
        __syncthreads();
        s[threadIdx.x] += t;
        __syncthreads();
    }
    g_partials[threadIdx.x] = s[threadIdx.x] - v;         // exclusive
}

__global__ void k_scan3() {  // add block prefixes; init cursor
    int i = blockIdx.x * 1024 + threadIdx.x;
    if (i < N_NODES) {
        int o = g_offsets[i] + g_partials[blockIdx.x];
        g_offsets[i] = o;
        g_cursor[i]  = o;
    }
}

__global__ void k_scatter(const int* __restrict__ dst) {
    int e = blockIdx.x * blockDim.x + threadIdx.x;
    if (e < N_EDGES) {
        int d = dst[e];
        int p = atomicAdd(&g_cursor[d], 1);
        g_perm[p] = e;
    }
}

// ---------------- kernel: gather-aggregate + residual + LayerNorm ----------------
// one warp per node, 4 features per lane (float4)
__global__ void __launch_bounds__(256)
k_agg(const int* __restrict__ esrc, const float* __restrict__ ew,
      const float* __restrict__ gamma, const float* __restrict__ beta,
      float* __restrict__ out) {
    int gwarp = (blockIdx.x * blockDim.x + threadIdx.x) >> 5;
    int lane  = threadIdx.x & 31;
    if (gwarp >= N_NODES) return;
    const int n = gwarp;

    const int start = g_offsets[n];
    const int end   = (n == N_NODES - 1) ? N_EDGES : g_offsets[n + 1];

    const float4* __restrict__ sup4 = (const float4*)g_support;
    float4 acc = ((const float4*)g_base)[(size_t)n * 32 + lane];

    for (int b = start; b < end; b += 32) {
        int e = b + lane;
        int s = 0; float w = 0.f;
        if (e < end) {
            int idx = g_perm[e];
            s = esrc[idx];
            w = ew[idx];
        }
        int cnt = min(32, end - b);
        if (cnt == 32) {
#pragma unroll 8
            for (int it = 0; it < 32; it++) {
                int   ss = __shfl_sync(0xffffffffu, s, it);
                float ww = __shfl_sync(0xffffffffu, w, it);
                float4 v = sup4[(size_t)ss * 32 + lane];
                acc.x = fmaf(ww, v.x, acc.x);
                acc.y = fmaf(ww, v.y, acc.y);
                acc.z = fmaf(ww, v.z, acc.z);
                acc.w = fmaf(ww, v.w, acc.w);
            }
        } else {
            for (int it = 0; it < cnt; it++) {
                int   ss = __shfl_sync(0xffffffffu, s, it);
                float ww = __shfl_sync(0xffffffffu, w, it);
                float4 v = sup4[(size_t)ss * 32 + lane];
                acc.x = fmaf(ww, v.x, acc.x);
                acc.y = fmaf(ww, v.y, acc.y);
                acc.z = fmaf(ww, v.z, acc.z);
                acc.w = fmaf(ww, v.w, acc.w);
            }
        }
    }

    // LayerNorm over 128 features (warp reduction)
    float psum = acc.x + acc.y + acc.z + acc.w;
#pragma unroll
    for (int o = 16; o; o >>= 1) psum += __shfl_xor_sync(0xffffffffu, psum, o);
    float mu = psum * (1.f / 128.f);

    float dx = acc.x - mu, dy = acc.y - mu, dz = acc.z - mu, dw = acc.w - mu;
    float pv = dx * dx + dy * dy + dz * dz + dw * dw;
#pragma unroll
    for (int o = 16; o; o >>= 1) pv += __shfl_xor_sync(0xffffffffu, pv, o);
    float rstd = rsqrtf(pv * (1.f / 128.f) + LN_EPS);

    float4 g  = ((const float4*)gamma)[lane];
    float4 bt = ((const float4*)beta)[lane];
    float4 o4;
    o4.x = dx * rstd * g.x + bt.x;
    o4.y = dy * rstd * g.y + bt.y;
    o4.z = dz * rstd * g.z + bt.z;
    o4.w = dw * rstd * g.w + bt.w;
    ((float4*)out)[(size_t)n * 32 + lane] = o4;
}

// ---------------- launcher ----------------
extern "C" void kernel_launch(void* const* d_in, const int* in_sizes, int n_in,
                              void* d_out, int out_size) {
    const float* x      = (const float*)d_in[0];
    const float* weight = (const float*)d_in[1];
    const float* bias   = (const float*)d_in[2];
    const float* res_w  = (const float*)d_in[3];
    const float* res_b  = (const float*)d_in[4];
    const float* gamma  = (const float*)d_in[5];
    const float* beta   = (const float*)d_in[6];
    const float* ew     = (const float*)d_in[7];
    const int*   eidx   = (const int*)d_in[8];
    const int* esrc = eidx;
    const int* edst = eidx + N_EDGES;
    float* out = (float*)d_out;

    const int nScanBlk = (N_NODES + 1023) / 1024;   // 98

    k_zero_count<<<(N_NODES + 1023) / 1024, 1024>>>();
    k_gemm<<<(N_NODES + BM - 1) / BM, 256>>>(x, weight, res_w, bias, res_b);
    k_hist<<<(N_EDGES + 255) / 256, 256>>>(edst);
    k_scan1<<<nScanBlk, 1024>>>();
    k_scan2<<<1, 128>>>();
    k_scan3<<<nScanBlk, 1024>>>();
    k_scatter<<<(N_EDGES + 255) / 256, 256>>>(edst);
    k_agg<<<(N_NODES * 32 + 255) / 256, 256>>>(esrc, ew, gamma, beta, out);
}

// round 8
// speedup vs baseline: 1.0025x; 1.0025x over previous
#include <cuda_runtime.h>

#define N_NODES 100000
#define N_EDGES 3200000
#define D_IN    256
#define D_OUT   128
#define LN_EPS  1e-5f

#define BM 64
#define BK 32

// ---------------- static device scratch (no runtime allocation) ----------------
__device__ float g_support[(size_t)N_NODES * D_OUT];   // x @ W
__device__ float g_base[(size_t)N_NODES * D_OUT];      // bias + relu(x @ res_w + res_b)
__device__ int   g_count[N_NODES];
__device__ int   g_offsets[N_NODES];
__device__ int   g_cursor[N_NODES];
__device__ int   g_perm[N_EDGES];
__device__ int   g_partials[128];

// ---------------- f32x2 packed-math helpers (FFMA2 path) ----------------
__device__ __forceinline__ unsigned long long dup2(float a) {
    unsigned long long r;
    unsigned int ai = __float_as_uint(a);
    asm("mov.b64 %0, {%1, %1};" : "=l"(r) : "r"(ai));
    return r;
}
__device__ __forceinline__ void fma2(unsigned long long& d, unsigned long long a,
                                     unsigned long long b) {
    asm("fma.rn.f32x2 %0, %1, %2, %0;" : "+l"(d) : "l"(a), "l"(b));
}
__device__ __forceinline__ float2 unpack2(unsigned long long v) {
    unsigned int lo, hi;
    asm("mov.b64 {%0, %1}, %2;" : "=r"(lo), "=r"(hi) : "l"(v));
    float2 r;
    r.x = __uint_as_float(lo);
    r.y = __uint_as_float(hi);
    return r;
}

// ---------------- kernel 1: fused dual GEMM ----------------
// support[n,:] = x[n,:] @ W          (D_IN x D_OUT)
// base[n,:]    = bias + relu(x[n,:] @ Rw + resb)
__global__ void __launch_bounds__(256, 2)
k_gemm(const float* __restrict__ x, const float* __restrict__ W,
       const float* __restrict__ Rw, const float* __restrict__ bias,
       const float* __restrict__ resb) {
    __shared__ float xs[BM][BK + 1];
    __shared__ __align__(16) float ws[BK][D_OUT];
    __shared__ __align__(16) float rs[BK][D_OUT];

    const int tid = threadIdx.x;          // 256 threads
    const int tx  = tid & 15;             // column group: cols tx*8 .. tx*8+7
    const int ty  = tid >> 4;             // rows ty + 16*i, i=0..3
    const int rowBase = blockIdx.x * BM;

    unsigned long long accW[4][4], accR[4][4];
#pragma unroll
    for (int i = 0; i < 4; i++)
#pragma unroll
        for (int j = 0; j < 4; j++) { accW[i][j] = 0ull; accR[i][j] = 0ull; }

    for (int k0 = 0; k0 < D_IN; k0 += BK) {
        // load x tile 64x32 (512 float4 -> 2 per thread), guard tail rows
#pragma unroll
        for (int f = tid; f < BM * BK / 4; f += 256) {
            int r = f >> 3;
            int c = (f & 7) * 4;
            float4 v = make_float4(0.f, 0.f, 0.f, 0.f);
            int row = rowBase + r;
            if (row < N_NODES)
                v = *(const float4*)(x + (size_t)row * D_IN + k0 + c);
            xs[r][c + 0] = v.x; xs[r][c + 1] = v.y;
            xs[r][c + 2] = v.z; xs[r][c + 3] = v.w;
        }
        // load W,R tiles 32x128 (1024 float4 each -> 4 per thread)
#pragma unroll
        for (int f = tid; f < BK * D_OUT / 4; f += 256) {
            int r = f >> 5;
            int c = (f & 31) * 4;
            *(float4*)&ws[r][c] = *(const float4*)(W  + (size_t)(k0 + r) * D_OUT + c);
            *(float4*)&rs[r][c] = *(const float4*)(Rw + (size_t)(k0 + r) * D_OUT + c);
        }
        __syncthreads();

#pragma unroll 8
        for (int k = 0; k < BK; k++) {
            unsigned long long a2[4];
#pragma unroll
            for (int i = 0; i < 4; i++) a2[i] = dup2(xs[ty + 16 * i][k]);
            // conflict-free LDS.128: 16 distinct 32B-aligned addresses per warp
            ulonglong2 w0 = *(const ulonglong2*)&ws[k][tx * 8];
            ulonglong2 w1 = *(const ulonglong2*)&ws[k][tx * 8 + 4];
            ulonglong2 r0 = *(const ulonglong2*)&rs[k][tx * 8];
            ulonglong2 r1 = *(const ulonglong2*)&rs[k][tx * 8 + 4];
#pragma unroll
            for (int i = 0; i < 4; i++) {
                fma2(accW[i][0], a2[i], w0.x);
                fma2(accW[i][1], a2[i], w0.y);
                fma2(accW[i][2], a2[i], w1.x);
                fma2(accW[i][3], a2[i], w1.y);
                fma2(accR[i][0], a2[i], r0.x);
                fma2(accR[i][1], a2[i], r0.y);
                fma2(accR[i][2], a2[i], r1.x);
                fma2(accR[i][3], a2[i], r1.y);
            }
        }
        __syncthreads();
    }

    // epilogue
    const float4 b0  = *(const float4*)(bias + tx * 8);
    const float4 b1  = *(const float4*)(bias + tx * 8 + 4);
    const float4 rb0 = *(const float4*)(resb + tx * 8);
    const float4 rb1 = *(const float4*)(resb + tx * 8 + 4);
#pragma unroll
    for (int i = 0; i < 4; i++) {
        int row = rowBase + ty + 16 * i;
        if (row >= N_NODES) continue;
        float2 s0 = unpack2(accW[i][0]), s1 = unpack2(accW[i][1]);
        float2 s2 = unpack2(accW[i][2]), s3 = unpack2(accW[i][3]);
        float2 t0 = unpack2(accR[i][0]), t1 = unpack2(accR[i][1]);
        float2 t2 = unpack2(accR[i][2]), t3 = unpack2(accR[i][3]);

        float* supp = g_support + (size_t)row * D_OUT + tx * 8;
        *(float4*)(supp)     = make_float4(s0.x, s0.y, s1.x, s1.y);
        *(float4*)(supp + 4) = make_float4(s2.x, s2.y, s3.x, s3.y);

        float* bp = g_base + (size_t)row * D_OUT + tx * 8;
        float4 bv0, bv1;
        bv0.x = b0.x + fmaxf(t0.x + rb0.x, 0.f);
        bv0.y = b0.y + fmaxf(t0.y + rb0.y, 0.f);
        bv0.z = b0.z + fmaxf(t1.x + rb0.z, 0.f);
        bv0.w = b0.w + fmaxf(t1.y + rb0.w, 0.f);
        bv1.x = b1.x + fmaxf(t2.x + rb1.x, 0.f);
        bv1.y = b1.y + fmaxf(t2.y + rb1.y, 0.f);
        bv1.z = b1.z + fmaxf(t3.x + rb1.z, 0.f);
        bv1.w = b1.w + fmaxf(t3.y + rb1.w, 0.f);
        *(float4*)(bp)     = bv0;
        *(float4*)(bp + 4) = bv1;
    }
}

// ---------------- counting sort pipeline ----------------
__global__ void k_zero_count() {
    int i = blockIdx.x * blockDim.x + threadIdx.x;
    if (i < N_NODES) g_count[i] = 0;
}

__global__ void k_hist(const int* __restrict__ dst) {
    int e = blockIdx.x * blockDim.x + threadIdx.x;
    if (e < N_EDGES) atomicAdd(&g_count[dst[e]], 1);
}

__global__ void k_scan1() {  // per-block exclusive scan, 98 blocks x 1024
    __shared__ int s[1024];
    int i = blockIdx.x * 1024 + threadIdx.x;
    int v = (i < N_NODES) ? g_count[i] : 0;
    s[threadIdx.x] = v;
    __syncthreads();
#pragma unroll
    for (int off = 1; off < 1024; off <<= 1) {
        int t = (threadIdx.x >= off) ? s[threadIdx.x - off] : 0;
        __syncthreads();
        s[threadIdx.x] += t;
        __syncthreads();
    }
    if (i < N_NODES) g_offsets[i] = s[threadIdx.x] - v;   // exclusive
    if (threadIdx.x == 1023) g_partials[blockIdx.x] = s[1023];
}

__global__ void k_scan2() {  // single block scans 98 partials (128 threads)
    __shared__ int s[128];
    int nblk = (N_NODES + 1023) / 1024;   // 98
    int v = (threadIdx.x < nblk) ? g_partials[threadIdx.x] : 0;
    s[threadIdx.x] = v;
    __syncthreads();
#pragma unroll
    for (int off = 1; off < 128; off <<= 1) {
        int t = (threadIdx.x >= off) ? s[threadIdx.x - off] : 0;
        __syncthreads();
        s[threadIdx.x] += t;
        __syncthreads();
    }
    g_partials[threadIdx.x] = s[threadIdx.x] - v;         // exclusive
}

__global__ void k_scan3() {  // add block prefixes; init cursor
    int i = blockIdx.x * 1024 + threadIdx.x;
    if (i < N_NODES) {
        int o = g_offsets[i] + g_partials[blockIdx.x];
        g_offsets[i] = o;
        g_cursor[i]  = o;
    }
}

__global__ void k_scatter(const int* __restrict__ dst) {
    int e = blockIdx.x * blockDim.x + threadIdx.x;
    if (e < N_EDGES) {
        int d = dst[e];
        int p = atomicAdd(&g_cursor[d], 1);
        g_perm[p] = e;
    }
}

// ---------------- kernel: gather-aggregate + residual + LayerNorm ----------------
// one warp per node, 4 features per lane (float4)
__global__ void __launch_bounds__(256)
k_agg(const int* __restrict__ esrc, const float* __restrict__ ew,
      const float* __restrict__ gamma, const float* __restrict__ beta,
      float* __restrict__ out) {
    int gwarp = (blockIdx.x * blockDim.x + threadIdx.x) >> 5;
    int lane  = threadIdx.x & 31;
    if (gwarp >= N_NODES) return;
    const int n = gwarp;

    const int start = g_offsets[n];
    const int end   = (n == N_NODES - 1) ? N_EDGES : g_offsets[n + 1];

    const float4* __restrict__ sup4 = (const float4*)g_support;
    float4 acc = ((const float4*)g_base)[(size_t)n * 32 + lane];

    for (int b = start; b < end; b += 32) {
        int e = b + lane;
        int s = 0; float w = 0.f;
        if (e < end) {
            int idx = g_perm[e];
            s = esrc[idx];
            w = ew[idx];
        }
        int cnt = min(32, end - b);
        if (cnt == 32) {
#pragma unroll 8
            for (int it = 0; it < 32; it++) {
                int   ss = __shfl_sync(0xffffffffu, s, it);
                float ww = __shfl_sync(0xffffffffu, w, it);
                float4 v = sup4[(size_t)ss * 32 + lane];
                acc.x = fmaf(ww, v.x, acc.x);
                acc.y = fmaf(ww, v.y, acc.y);
                acc.z = fmaf(ww, v.z, acc.z);
                acc.w = fmaf(ww, v.w, acc.w);
            }
        } else {
            for (int it = 0; it < cnt; it++) {
                int   ss = __shfl_sync(0xffffffffu, s, it);
                float ww = __shfl_sync(0xffffffffu, w, it);
                float4 v = sup4[(size_t)ss * 32 + lane];
                acc.x = fmaf(ww, v.x, acc.x);
                acc.y = fmaf(ww, v.y, acc.y);
                acc.z = fmaf(ww, v.z, acc.z);
                acc.w = fmaf(ww, v.w, acc.w);
            }
        }
    }

    // LayerNorm over 128 features (warp reduction)
    float psum = acc.x + acc.y + acc.z + acc.w;
#pragma unroll
    for (int o = 16; o; o >>= 1) psum += __shfl_xor_sync(0xffffffffu, psum, o);
    float mu = psum * (1.f / 128.f);

    float dx = acc.x - mu, dy = acc.y - mu, dz = acc.z - mu, dw = acc.w - mu;
    float pv = dx * dx + dy * dy + dz * dz + dw * dw;
#pragma unroll
    for (int o = 16; o; o >>= 1) pv += __shfl_xor_sync(0xffffffffu, pv, o);
    float rstd = rsqrtf(pv * (1.f / 128.f) + LN_EPS);

    float4 g  = ((const float4*)gamma)[lane];
    float4 bt = ((const float4*)beta)[lane];
    float4 o4;
    o4.x = dx * rstd * g.x + bt.x;
    o4.y = dy * rstd * g.y + bt.y;
    o4.z = dz * rstd * g.z + bt.z;
    o4.w = dw * rstd * g.w + bt.w;
    ((float4*)out)[(size_t)n * 32 + lane] = o4;
}

// ---------------- launcher ----------------
extern "C" void kernel_launch(void* const* d_in, const int* in_sizes, int n_in,
                              void* d_out, int out_size) {
    const float* x      = (const float*)d_in[0];
    const float* weight = (const float*)d_in[1];
    const float* bias   = (const float*)d_in[2];
    const float* res_w  = (const float*)d_in[3];
    const float* res_b  = (const float*)d_in[4];
    const float* gamma  = (const float*)d_in[5];
    const float* beta   = (const float*)d_in[6];
    const float* ew     = (const float*)d_in[7];
    const int*   eidx   = (const int*)d_in[8];
    const int* esrc = eidx;
    const int* edst = eidx + N_EDGES;
    float* out = (float*)d_out;

    const int nScanBlk = (N_NODES + 1023) / 1024;   // 98

    k_zero_count<<<(N_NODES + 1023) / 1024, 1024>>>();
    k_gemm<<<(N_NODES + BM - 1) / BM, 256>>>(x, weight, res_w, bias, res_b);
    k_hist<<<(N_EDGES + 255) / 256, 256>>>(edst);
    k_scan1<<<nScanBlk, 1024>>>();
    k_scan2<<<1, 128>>>();
    k_scan3<<<nScanBlk, 1024>>>();
    k_scatter<<<(N_EDGES + 255) / 256, 256>>>(edst);
    k_agg<<<(N_NODES * 32 + 255) / 256, 256>>>(esrc, ew, gamma, beta, out);
}

// round 9
// speedup vs baseline: 1.0037x; 1.0012x over previous
#include <cuda_runtime.h>

#define N_NODES 100000
#define N_EDGES 3200000
#define D_IN    256
#define D_OUT   128
#define LN_EPS  1e-5f

#define BM 64
#define BK 32

// ---------------- static device scratch (no runtime allocation) ----------------
__device__ float g_support[(size_t)N_NODES * D_OUT];   // x @ W
__device__ float g_base[(size_t)N_NODES * D_OUT];      // bias + relu(x @ res_w + res_b)
__device__ int   g_count[N_NODES];
__device__ int   g_offsets[N_NODES];
__device__ int   g_cursor[N_NODES];
__device__ int   g_perm[N_EDGES];
__device__ int   g_partials[128];

// ---------------- f32x2 packed-math helpers (FFMA2 path) ----------------
__device__ __forceinline__ unsigned long long dup2(float a) {
    unsigned long long r;
    unsigned int ai = __float_as_uint(a);
    asm("mov.b64 %0, {%1, %1};" : "=l"(r) : "r"(ai));
    return r;
}
__device__ __forceinline__ void fma2(unsigned long long& d, unsigned long long a,
                                     unsigned long long b) {
    asm("fma.rn.f32x2 %0, %1, %2, %0;" : "+l"(d) : "l"(a), "l"(b));
}
__device__ __forceinline__ float2 unpack2(unsigned long long v) {
    unsigned int lo, hi;
    asm("mov.b64 {%0, %1}, %2;" : "=r"(lo), "=r"(hi) : "l"(v));
    float2 r;
    r.x = __uint_as_float(lo);
    r.y = __uint_as_float(hi);
    return r;
}

// ---------------- kernel 1: fused dual GEMM ----------------
// support[n,:] = x[n,:] @ W          (D_IN x D_OUT)
// base[n,:]    = bias + relu(x[n,:] @ Rw + resb)
__global__ void __launch_bounds__(256, 2)
k_gemm(const float* __restrict__ x, const float* __restrict__ W,
       const float* __restrict__ Rw, const float* __restrict__ bias,
       const float* __restrict__ resb) {
    __shared__ float xs[BM][BK + 1];
    __shared__ __align__(16) float ws[BK][D_OUT];
    __shared__ __align__(16) float rs[BK][D_OUT];

    const int tid = threadIdx.x;          // 256 threads
    const int tx  = tid & 15;             // column group: cols tx*8 .. tx*8+7
    const int ty  = tid >> 4;             // rows ty + 16*i, i=0..3
    const int rowBase = blockIdx.x * BM;

    unsigned long long accW[4][4], accR[4][4];
#pragma unroll
    for (int i = 0; i < 4; i++)
#pragma unroll
        for (int j = 0; j < 4; j++) { accW[i][j] = 0ull; accR[i][j] = 0ull; }

    for (int k0 = 0; k0 < D_IN; k0 += BK) {
        // load x tile 64x32 (512 float4 -> 2 per thread), guard tail rows
#pragma unroll
        for (int f = tid; f < BM * BK / 4; f += 256) {
            int r = f >> 3;
            int c = (f & 7) * 4;
            float4 v = make_float4(0.f, 0.f, 0.f, 0.f);
            int row = rowBase + r;
            if (row < N_NODES)
                v = *(const float4*)(x + (size_t)row * D_IN + k0 + c);
            xs[r][c + 0] = v.x; xs[r][c + 1] = v.y;
            xs[r][c + 2] = v.z; xs[r][c + 3] = v.w;
        }
        // load W,R tiles 32x128 (1024 float4 each -> 4 per thread)
#pragma unroll
        for (int f = tid; f < BK * D_OUT / 4; f += 256) {
            int r = f >> 5;
            int c = (f & 31) * 4;
            *(float4*)&ws[r][c] = *(const float4*)(W  + (size_t)(k0 + r) * D_OUT + c);
            *(float4*)&rs[r][c] = *(const float4*)(Rw + (size_t)(k0 + r) * D_OUT + c);
        }
        __syncthreads();

#pragma unroll 8
        for (int k = 0; k < BK; k++) {
            unsigned long long a2[4];
#pragma unroll
            for (int i = 0; i < 4; i++) a2[i] = dup2(xs[ty + 16 * i][k]);
            // conflict-free LDS.128: 16 distinct 32B-aligned addresses per warp
            ulonglong2 w0 = *(const ulonglong2*)&ws[k][tx * 8];
            ulonglong2 w1 = *(const ulonglong2*)&ws[k][tx * 8 + 4];
            ulonglong2 r0 = *(const ulonglong2*)&rs[k][tx * 8];
            ulonglong2 r1 = *(const ulonglong2*)&rs[k][tx * 8 + 4];
#pragma unroll
            for (int i = 0; i < 4; i++) {
                fma2(accW[i][0], a2[i], w0.x);
                fma2(accW[i][1], a2[i], w0.y);
                fma2(accW[i][2], a2[i], w1.x);
                fma2(accW[i][3], a2[i], w1.y);
                fma2(accR[i][0], a2[i], r0.x);
                fma2(accR[i][1], a2[i], r0.y);
                fma2(accR[i][2], a2[i], r1.x);
                fma2(accR[i][3], a2[i], r1.y);
            }
        }
        __syncthreads();
    }

    // epilogue
    const float4 b0  = *(const float4*)(bias + tx * 8);
    const float4 b1  = *(const float4*)(bias + tx * 8 + 4);
    const float4 rb0 = *(const float4*)(resb + tx * 8);
    const float4 rb1 = *(const float4*)(resb + tx * 8 + 4);
#pragma unroll
    for (int i = 0; i < 4; i++) {
        int row = rowBase + ty + 16 * i;
        if (row >= N_NODES) continue;
        float2 s0 = unpack2(accW[i][0]), s1 = unpack2(accW[i][1]);
        float2 s2 = unpack2(accW[i][2]), s3 = unpack2(accW[i][3]);
        float2 t0 = unpack2(accR[i][0]), t1 = unpack2(accR[i][1]);
        float2 t2 = unpack2(accR[i][2]), t3 = unpack2(accR[i][3]);

        float* supp = g_support + (size_t)row * D_OUT + tx * 8;
        *(float4*)(supp)     = make_float4(s0.x, s0.y, s1.x, s1.y);
        *(float4*)(supp + 4) = make_float4(s2.x, s2.y, s3.x, s3.y);

        float* bp = g_base + (size_t)row * D_OUT + tx * 8;
        float4 bv0, bv1;
        bv0.x = b0.x + fmaxf(t0.x + rb0.x, 0.f);
        bv0.y = b0.y + fmaxf(t0.y + rb0.y, 0.f);
        bv0.z = b0.z + fmaxf(t1.x + rb0.z, 0.f);
        bv0.w = b0.w + fmaxf(t1.y + rb0.w, 0.f);
        bv1.x = b1.x + fmaxf(t2.x + rb1.x, 0.f);
        bv1.y = b1.y + fmaxf(t2.y + rb1.y, 0.f);
        bv1.z = b1.z + fmaxf(t3.x + rb1.z, 0.f);
        bv1.w = b1.w + fmaxf(t3.y + rb1.w, 0.f);
        *(float4*)(bp)     = bv0;
        *(float4*)(bp + 4) = bv1;
    }
}

// ---------------- counting sort pipeline ----------------
__global__ void k_zero_count() {
    int i = blockIdx.x * blockDim.x + threadIdx.x;
    if (i < N_NODES) g_count[i] = 0;
}

__global__ void k_hist(const int* __restrict__ dst) {
    int e = blockIdx.x * blockDim.x + threadIdx.x;
    if (e < N_EDGES) atomicAdd(&g_count[dst[e]], 1);
}

__global__ void k_scan1() {  // per-block exclusive scan, 98 blocks x 1024
    __shared__ int s[1024];
    int i = blockIdx.x * 1024 + threadIdx.x;
    int v = (i < N_NODES) ? g_count[i] : 0;
    s[threadIdx.x] = v;
    __syncthreads();
#pragma unroll
    for (int off = 1; off < 1024; off <<= 1) {
        int t = (threadIdx.x >= off) ? s[threadIdx.x - off] : 0;
        __syncthreads();
        s[threadIdx.x] += t;
        __syncthreads();
    }
    if (i < N_NODES) g_offsets[i] = s[threadIdx.x] - v;   // exclusive
    if (threadIdx.x == 1023) g_partials[blockIdx.x] = s[1023];
}

__global__ void k_scan2() {  // single block scans 98 partials (128 threads)
    __shared__ int s[128];
    int nblk = (N_NODES + 1023) / 1024;   // 98
    int v = (threadIdx.x < nblk) ? g_partials[threadIdx.x] : 0;
    s[threadIdx.x] = v;
    __syncthreads();
#pragma unroll
    for (int off = 1; off < 128; off <<= 1) {
        int t = (threadIdx.x >= off) ? s[threadIdx.x - off] : 0;
        __syncthreads();
        s[threadIdx.x] += t;
        __syncthreads();
    }
    g_partials[threadIdx.x] = s[threadIdx.x] - v;         // exclusive
}

__global__ void k_scan3() {  // add block prefixes; init cursor
    int i = blockIdx.x * 1024 + threadIdx.x;
    if (i < N_NODES) {
        int o = g_offsets[i] + g_partials[blockIdx.x];
        g_offsets[i] = o;
        g_cursor[i]  = o;
    }
}

__global__ void k_scatter(const int* __restrict__ dst) {
    int e = blockIdx.x * blockDim.x + threadIdx.x;
    if (e < N_EDGES) {
        int d = dst[e];
        int p = atomicAdd(&g_cursor[d], 1);
        g_perm[p] = e;
    }
}

// ---------------- kernel: gather-aggregate + residual + LayerNorm ----------------
// one warp per node, 4 features per lane (float4)
__global__ void __launch_bounds__(256)
k_agg(const int* __restrict__ esrc, const float* __restrict__ ew,
      const float* __restrict__ gamma, const float* __restrict__ beta,
      float* __restrict__ out) {
    int gwarp = (blockIdx.x * blockDim.x + threadIdx.x) >> 5;
    int lane  = threadIdx.x & 31;
    if (gwarp >= N_NODES) return;
    const int n = gwarp;

    const int start = g_offsets[n];
    const int end   = (n == N_NODES - 1) ? N_EDGES : g_offsets[n + 1];

    const float4* __restrict__ sup4 = (const float4*)g_support;
    float4 acc = ((const float4*)g_base)[(size_t)n * 32 + lane];

    for (int b = start; b < end; b += 32) {
        int e = b + lane;
        int s = 0; float w = 0.f;
        if (e < end) {
            int idx = g_perm[e];
            s = esrc[idx];
            w = ew[idx];
        }
        int cnt = min(32, end - b);
        if (cnt == 32) {
#pragma unroll 8
            for (int it = 0; it < 32; it++) {
                int   ss = __shfl_sync(0xffffffffu, s, it);
                float ww = __shfl_sync(0xffffffffu, w, it);
                float4 v = sup4[(size_t)ss * 32 + lane];
                acc.x = fmaf(ww, v.x, acc.x);
                acc.y = fmaf(ww, v.y, acc.y);
                acc.z = fmaf(ww, v.z, acc.z);
                acc.w = fmaf(ww, v.w, acc.w);
            }
        } else {
            for (int it = 0; it < cnt; it++) {
                int   ss = __shfl_sync(0xffffffffu, s, it);
                float ww = __shfl_sync(0xffffffffu, w, it);
                float4 v = sup4[(size_t)ss * 32 + lane];
                acc.x = fmaf(ww, v.x, acc.x);
                acc.y = fmaf(ww, v.y, acc.y);
                acc.z = fmaf(ww, v.z, acc.z);
                acc.w = fmaf(ww, v.w, acc.w);
            }
        }
    }

    // LayerNorm over 128 features (warp reduction)
    float psum = acc.x + acc.y + acc.z + acc.w;
#pragma unroll
    for (int o = 16; o; o >>= 1) psum += __shfl_xor_sync(0xffffffffu, psum, o);
    float mu = psum * (1.f / 128.f);

    float dx = acc.x - mu, dy = acc.y - mu, dz = acc.z - mu, dw = acc.w - mu;
    float pv = dx * dx + dy * dy + dz * dz + dw * dw;
#pragma unroll
    for (int o = 16; o; o >>= 1) pv += __shfl_xor_sync(0xffffffffu, pv, o);
    float rstd = rsqrtf(pv * (1.f / 128.f) + LN_EPS);

    float4 g  = ((const float4*)gamma)[lane];
    float4 bt = ((const float4*)beta)[lane];
    float4 o4;
    o4.x = dx * rstd * g.x + bt.x;
    o4.y = dy * rstd * g.y + bt.y;
    o4.z = dz * rstd * g.z + bt.z;
    o4.w = dw * rstd * g.w + bt.w;
    ((float4*)out)[(size_t)n * 32 + lane] = o4;
}

// ---------------- launcher ----------------
extern "C" void kernel_launch(void* const* d_in, const int* in_sizes, int n_in,
                              void* d_out, int out_size) {
    const float* x      = (const float*)d_in[0];
    const float* weight = (const float*)d_in[1];
    const float* bias   = (const float*)d_in[2];
    const float* res_w  = (const float*)d_in[3];
    const float* res_b  = (const float*)d_in[4];
    const float* gamma  = (const float*)d_in[5];
    const float* beta   = (const float*)d_in[6];
    const float* ew     = (const float*)d_in[7];
    const int*   eidx   = (const int*)d_in[8];
    const int* esrc = eidx;
    const int* edst = eidx + N_EDGES;
    float* out = (float*)d_out;

    const int nScanBlk = (N_NODES + 1023) / 1024;   // 98

    k_zero_count<<<(N_NODES + 1023) / 1024, 1024>>>();
    k_gemm<<<(N_NODES + BM - 1) / BM, 256>>>(x, weight, res_w, bias, res_b);
    k_hist<<<(N_EDGES + 255) / 256, 256>>>(edst);
    k_scan1<<<nScanBlk, 1024>>>();
    k_scan2<<<1, 128>>>();
    k_scan3<<<nScanBlk, 1024>>>();
    k_scatter<<<(N_EDGES + 255) / 256, 256>>>(edst);
    k_agg<<<(N_NODES * 32 + 255) / 256, 256>>>(esrc, ew, gamma, beta, out);
}